// round 15
// baseline (speedup 1.0000x reference)
#include <cuda_runtime.h>
#include <cuda_bf16.h>

// DeformableConvLayer: B=4, H=W=256, C=64, K=3x3, UNITS=1.
// Two kernels overlapped via PDL, with P2 shrunk to half-row 128-thread blocks
// (15.7 KB smem) so P2 CTAs CO-RESIDE with P1 (which leaves 22 KB/SM free).
//   P1: R9 double-buffered contraction, launch_dependents at entry,
//       red.release per-batch counter after plane stores.
//   P2: half-row select-gather; stages offset/mask (P1-independent), then
//       acquire-spins on its batch counter; self-cleaning counters.

namespace {

constexpr int Hc = 256;
constexpr int Wc = 256;
constexpr int PIX = 4 * Hc * Wc;               // 262144

__device__ float g_P[9 * PIX];                 // 9.4 MB tap-plane scratch
__device__ int   g_done[4];                    // P1 blocks done per batch (512)
__device__ int   g_p2done[4];                  // P2 blocks done per batch (512)

__device__ __forceinline__ unsigned long long fma2(unsigned long long a,
                                                   unsigned long long b,
                                                   unsigned long long c)
{
    unsigned long long d;
    asm("fma.rn.f32x2 %0, %1, %2, %3;" : "=l"(d) : "l"(a), "l"(b), "l"(c));
    return d;
}

// ---------------- Phase 1: double-buffered contraction (R9) ----------------
constexpr int P1_T = 128;

__global__ __launch_bounds__(P1_T)
void dcn_phase1(const float* __restrict__ input,   // [PIX, 64]
                const float* __restrict__ kern)    // [9, 64]
{
    asm volatile("griddepcontrol.launch_dependents;" ::: "memory");

    __shared__ float4 in_s[2][P1_T * 8];  // 2 x 16 KB, [pixel][c4 ^ (pixel&7)]
    __shared__ float4 w_s[9 * 16];        // 2.3 KB

    const int t = threadIdx.x;
    const int pixbase = blockIdx.x * P1_T;

    for (int i = t; i < 9 * 16; i += P1_T)
        w_s[i] = reinterpret_cast<const float4*>(kern)[i];

    const float4* in4 = reinterpret_cast<const float4*>(input) + (size_t)pixbase * 16;

#pragma unroll
    for (int half = 0; half < 2; half++) {
#pragma unroll
        for (int i = 0; i < 8; i++) {
            const int g  = i * P1_T + t;
            const int p  = g >> 3;
            const int c4 = g & 7;
            const float4* src = &in4[(size_t)p * 16 + half * 8 + c4];
            float4* dst = &in_s[half][p * 8 + (c4 ^ (p & 7))];
            const unsigned sdst = (unsigned)__cvta_generic_to_shared(dst);
            asm volatile("cp.async.cg.shared.global [%0], [%1], 16;\n"
                         :: "r"(sdst), "l"(src));
        }
        asm volatile("cp.async.commit_group;\n");
    }

    unsigned long long acc2[9];
#pragma unroll
    for (int k = 0; k < 9; k++) acc2[k] = 0ull;

    asm volatile("cp.async.wait_group 1;\n" ::: "memory");
    __syncthreads();
#pragma unroll
    for (int c4 = 0; c4 < 8; c4++) {
        const ulonglong2 v = *reinterpret_cast<const ulonglong2*>(
                                 &in_s[0][t * 8 + (c4 ^ (t & 7))]);
#pragma unroll
        for (int k = 0; k < 9; k++) {
            const ulonglong2 wv = *reinterpret_cast<const ulonglong2*>(&w_s[k * 16 + c4]);
            acc2[k] = fma2(v.x, wv.x, acc2[k]);
            acc2[k] = fma2(v.y, wv.y, acc2[k]);
        }
    }

    asm volatile("cp.async.wait_group 0;\n" ::: "memory");
    __syncthreads();
#pragma unroll
    for (int c4 = 0; c4 < 8; c4++) {
        const ulonglong2 v = *reinterpret_cast<const ulonglong2*>(
                                 &in_s[1][t * 8 + (c4 ^ (t & 7))]);
#pragma unroll
        for (int k = 0; k < 9; k++) {
            const ulonglong2 wv = *reinterpret_cast<const ulonglong2*>(&w_s[k * 16 + 8 + c4]);
            acc2[k] = fma2(v.x, wv.x, acc2[k]);
            acc2[k] = fma2(v.y, wv.y, acc2[k]);
        }
    }

#pragma unroll
    for (int k = 0; k < 9; k++) {
        float lo, hi;
        asm("mov.b64 {%0, %1}, %2;" : "=f"(lo), "=f"(hi) : "l"(acc2[k]));
        g_P[k * PIX + pixbase + t] = lo + hi;
    }

    __threadfence();
    __syncthreads();
    if (t == 0) {
        const int batch = blockIdx.x >> 9;        // 512 P1 blocks per batch
        asm volatile("red.release.gpu.global.add.s32 [%0], 1;"
                     :: "l"(&g_done[batch]) : "memory");
    }
}

// ---------------- Phase 2: half-row select-gather (co-residable) ----------------
constexpr int P2_T = 128;   // half a row per block; ~15.7 KB smem

__global__ __launch_bounds__(P2_T)
void dcn_phase2(const float* __restrict__ mask,     // [256,256]
                const float* __restrict__ offset,   // [PIX,18]
                const float* __restrict__ bias,
                float* __restrict__ out)            // [PIX]
{
    __shared__ float soff[P2_T * 18];    // 9.2 KB offsets for this half-row
    __shared__ float smask[3 * 136];     // base-mask rows h-2..h, cols w0-2..w0+133
    __shared__ float sP[9 * 136];        // base-tap P rows: plane k, row h+ky-2

    const int t = threadIdx.x;
    const int pix0 = blockIdx.x * P2_T;
    const int b  = pix0 >> 16;
    const int h  = (pix0 >> 8) & 255;
    const int w0 = pix0 & 255;           // 0 or 128
    const int w  = w0 + t;
    const float* Pb = g_P + (size_t)b * (Hc * Wc);

    // ---- P1-independent staging (overlaps P1) ----
    {   // offsets: 576 float4, coalesced
        const float4* off4 = reinterpret_cast<const float4*>(offset + (size_t)pix0 * 18);
        float4* soff4 = reinterpret_cast<float4*>(soff);
#pragma unroll
        for (int i = 0; i < 4; i++)
            soff4[i * P2_T + t] = off4[i * P2_T + t];
        if (t < 576 - 4 * P2_T)
            soff4[4 * P2_T + t] = off4[4 * P2_T + t];
    }
    for (int i = t; i < 3 * 136; i += P2_T) {
        const int r = i / 136, c = i - r * 136;
        const int row = h - 2 + r, col = w0 - 2 + c;
        smask[i] = (row >= 0 && col >= 0 && col <= 255) ? mask[row * Wc + col] : 0.0f;
    }

    // ---- wait for this batch's planes ----
    if (t == 0) {
        int v;
        do {
            asm volatile("ld.acquire.gpu.global.b32 %0, [%1];"
                         : "=r"(v) : "l"(&g_done[b]) : "memory");
            if (v < 512) __nanosleep(64);
        } while (v < 512);
    }
    __syncthreads();

    // base-tap P rows (planes final after spin)
    for (int i = t; i < 9 * 136; i += P2_T) {
        const int k = i / 136, c = i - k * 136;
        const int row = h + k / 3 - 2, col = w0 - 2 + c;
        sP[i] = (row >= 0 && col >= 0 && col <= 255)
                    ? g_P[k * PIX + b * (Hc * Wc) + row * Wc + col] : 0.0f;
    }
    __syncthreads();

    // ---- single wave: 9 offset-path P gathers + 9 offset-mask gathers ----
    float Vo[9], pmoff[9];
#pragma unroll
    for (int k = 0; k < 9; k++) {
        const int ky = k / 3;
        const int kx = k - ky * 3;
        const int yb = h + ky - 1;
        const int xb = w + kx - 1;
        const bool inb = (yb >= 0) & (yb < Hc) & (xb >= 0) & (xb < Wc);
        const int yi = inb ? yb : 0;
        const int xi = inb ? xb : 0;

        const float2 off2 = *reinterpret_cast<const float2*>(&soff[t * 18 + 2 * k]);

        const float yf = fminf(fmaxf((float)yi + off2.x, 0.0f), 255.0f);
        const float xf = fminf(fmaxf((float)xi + off2.y, 0.0f), 255.0f);
        const int y0 = (int)floorf(yf);
        const int x0 = (int)floorf(xf);
        Vo[k] = ((y0 >= 1) & (x0 >= 1))
                    ? Pb[k * PIX + (y0 - 1) * Wc + (x0 - 1)] : 0.0f;

        int yo = (int)floorf((float)yi + off2.x);
        int xo = (int)floorf((float)xi + off2.y);
        yo = min(max(yo, 0), Hc + 1);
        xo = min(max(xo, 0), Wc + 1);
        pmoff[k] = ((yo >= 1) & (yo <= Hc) & (xo >= 1) & (xo <= Wc))
                       ? mask[(yo - 1) * Wc + (xo - 1)] : 0.0f;
    }

    // ---- select + sum ----
    float acc = __ldg(bias);
#pragma unroll
    for (int k = 0; k < 9; k++) {
        const int ky = k / 3;
        const int kx = k - ky * 3;
        const int yb = h + ky - 1;
        const int xb = w + kx - 1;
        const bool base_ok = (yb >= 1) & (yb < Hc) & (xb >= 1) & (xb < Wc);
        const float pmask = base_ok ? smask[ky * 136 + (t + kx)] : 0.0f;
        const float Vb    = base_ok ? sP[k * 136 + (t + kx)] : 0.0f;
        acc += (pmask != pmoff[k]) ? Vo[k] : Vb;
    }

    out[pix0 + t] = acc;

    // ---- self-cleaning counters (graph-replay deterministic) ----
    __syncthreads();
    if (t == 0) {
        const int old = atomicAdd(&g_p2done[b], 1);
        if (old == 511) {                 // 512 P2 blocks per batch
            atomicExch(&g_done[b], 0);
            atomicExch(&g_p2done[b], 0);
        }
    }
}

} // namespace

extern "C" void kernel_launch(void* const* d_in, const int* in_sizes, int n_in,
                              void* d_out, int out_size)
{
    const float* input  = (const float*)d_in[0];   // [4,256,256,64]
    const float* mask   = (const float*)d_in[1];   // [1,256,256,1]
    const float* offset = (const float*)d_in[2];   // [4,256,256,18]
    const float* kern   = (const float*)d_in[3];   // [3,3,64,1]
    const float* bias   = (const float*)d_in[4];   // [1]
    float* out = (float*)d_out;

    dcn_phase1<<<PIX / P1_T, P1_T>>>(input, kern);

    cudaLaunchConfig_t cfg = {};
    cfg.gridDim  = dim3(PIX / P2_T);
    cfg.blockDim = dim3(P2_T);
    cfg.dynamicSmemBytes = 0;
    cfg.stream = 0;
    cudaLaunchAttribute attrs[1];
    attrs[0].id = cudaLaunchAttributeProgrammaticStreamSerialization;
    attrs[0].val.programmaticStreamSerializationAllowed = 1;
    cfg.attrs = attrs;
    cfg.numAttrs = 1;
    cudaLaunchKernelEx(&cfg, dcn_phase2, mask, offset, bias, (float*)out);
}

// round 16
// speedup vs baseline: 1.3282x; 1.3282x over previous
#include <cuda_runtime.h>
#include <cuda_bf16.h>

// DeformableConvLayer: B=4, H=W=256, C=64, K=3x3, UNITS=1.
// Best-known configuration (R14) + P1 prologue reorder:
//   P1: double-buffered cp.async contraction; cp.async groups issued FIRST
//       (DRAM stream starts immediately; weight staging overlaps it).
//       PDL launch_dependents at entry; red.release per-batch counter.
//   P2: R6/R9 one-wave select-gather (proven 12.1us optimum), acquire-spin
//       on its batch counter; self-cleaning counters (graph-replay safe).
// Overlap experiments (fused kernel, co-residable P2) are closed: every
// variant lost through shared registers / smem slots / scheduler order.

namespace {

constexpr int Hc = 256;
constexpr int Wc = 256;
constexpr int PIX = 4 * Hc * Wc;               // 262144

__device__ float g_P[9 * PIX];                 // 9.4 MB tap-plane scratch
__device__ int   g_done[4];                    // P1 blocks done per batch (512)
__device__ int   g_p2done[4];                  // P2 blocks done per batch (256)

__device__ __forceinline__ unsigned long long fma2(unsigned long long a,
                                                   unsigned long long b,
                                                   unsigned long long c)
{
    unsigned long long d;
    asm("fma.rn.f32x2 %0, %1, %2, %3;" : "=l"(d) : "l"(a), "l"(b), "l"(c));
    return d;
}

// ---------------- Phase 1: double-buffered contraction ----------------
constexpr int P1_T = 128;

__global__ __launch_bounds__(P1_T)
void dcn_phase1(const float* __restrict__ input,   // [PIX, 64]
                const float* __restrict__ kern)    // [9, 64]
{
    asm volatile("griddepcontrol.launch_dependents;" ::: "memory");

    __shared__ float4 in_s[2][P1_T * 8];  // 2 x 16 KB, [pixel][c4 ^ (pixel&7)]
    __shared__ float4 w_s[9 * 16];        // 2.3 KB

    const int t = threadIdx.x;
    const int pixbase = blockIdx.x * P1_T;

    const float4* in4 = reinterpret_cast<const float4*>(input) + (size_t)pixbase * 16;

    // Issue BOTH cp.async halves FIRST — the DRAM stream starts before any
    // dependent weight loads; weight staging overlaps the in-flight copies.
#pragma unroll
    for (int half = 0; half < 2; half++) {
#pragma unroll
        for (int i = 0; i < 8; i++) {
            const int g  = i * P1_T + t;
            const int p  = g >> 3;
            const int c4 = g & 7;
            const float4* src = &in4[(size_t)p * 16 + half * 8 + c4];
            float4* dst = &in_s[half][p * 8 + (c4 ^ (p & 7))];
            const unsigned sdst = (unsigned)__cvta_generic_to_shared(dst);
            asm volatile("cp.async.cg.shared.global [%0], [%1], 16;\n"
                         :: "r"(sdst), "l"(src));
        }
        asm volatile("cp.async.commit_group;\n");
    }

    // Weight staging (overlaps the async copies above).
    for (int i = t; i < 9 * 16; i += P1_T)
        w_s[i] = reinterpret_cast<const float4*>(kern)[i];

    unsigned long long acc2[9];
#pragma unroll
    for (int k = 0; k < 9; k++) acc2[k] = 0ull;

    asm volatile("cp.async.wait_group 1;\n" ::: "memory");
    __syncthreads();
#pragma unroll
    for (int c4 = 0; c4 < 8; c4++) {
        const ulonglong2 v = *reinterpret_cast<const ulonglong2*>(
                                 &in_s[0][t * 8 + (c4 ^ (t & 7))]);
#pragma unroll
        for (int k = 0; k < 9; k++) {
            const ulonglong2 wv = *reinterpret_cast<const ulonglong2*>(&w_s[k * 16 + c4]);
            acc2[k] = fma2(v.x, wv.x, acc2[k]);
            acc2[k] = fma2(v.y, wv.y, acc2[k]);
        }
    }

    asm volatile("cp.async.wait_group 0;\n" ::: "memory");
    __syncthreads();
#pragma unroll
    for (int c4 = 0; c4 < 8; c4++) {
        const ulonglong2 v = *reinterpret_cast<const ulonglong2*>(
                                 &in_s[1][t * 8 + (c4 ^ (t & 7))]);
#pragma unroll
        for (int k = 0; k < 9; k++) {
            const ulonglong2 wv = *reinterpret_cast<const ulonglong2*>(&w_s[k * 16 + 8 + c4]);
            acc2[k] = fma2(v.x, wv.x, acc2[k]);
            acc2[k] = fma2(v.y, wv.y, acc2[k]);
        }
    }

#pragma unroll
    for (int k = 0; k < 9; k++) {
        float lo, hi;
        asm("mov.b64 {%0, %1}, %2;" : "=f"(lo), "=f"(hi) : "l"(acc2[k]));
        g_P[k * PIX + pixbase + t] = lo + hi;
    }

    __threadfence();
    __syncthreads();
    if (t == 0) {
        const int batch = blockIdx.x >> 9;        // 512 P1 blocks per batch
        asm volatile("red.release.gpu.global.add.s32 [%0], 1;"
                     :: "l"(&g_done[batch]) : "memory");
    }
}

// ---------------- Phase 2: one-wave select-gather (R9) + acquire-spin ----------------
constexpr int P2_T = 256;

__global__ __launch_bounds__(P2_T)
void dcn_phase2(const float* __restrict__ mask,     // [256,256]
                const float* __restrict__ offset,   // [PIX,18]
                const float* __restrict__ bias,
                float* __restrict__ out)            // [PIX]
{
    __shared__ float soff[P2_T * 18];    // 18 KB offsets for this row
    __shared__ float smask[3 * 256];     // base-mask rows h-2..h
    __shared__ float sP[9 * 256];        // base-tap P rows: plane k, row h+ky-2

    const int t = threadIdx.x;
    const int pixbase = blockIdx.x * P2_T;   // one image row per block
    const int b = pixbase >> 16;
    const int h = (pixbase >> 8) & 255;
    const int w = t;
    const float* Pb = g_P + (size_t)b * (Hc * Wc);

    // ---- P1-independent staging ----
    {   // offsets: 1152 float4, coalesced
        const float4* off4 = reinterpret_cast<const float4*>(offset + (size_t)pixbase * 18);
        float4* soff4 = reinterpret_cast<float4*>(soff);
#pragma unroll
        for (int i = 0; i < 4; i++)
            soff4[i * P2_T + t] = off4[i * P2_T + t];
        if (t < 1152 - 4 * P2_T)
            soff4[4 * P2_T + t] = off4[4 * P2_T + t];
    }
#pragma unroll
    for (int r = 0; r < 3; r++) {
        const int row = h - 2 + r;
        smask[r * 256 + t] = (row >= 0) ? mask[row * Wc + t] : 0.0f;
    }

    // ---- wait for this batch's planes ----
    if (t == 0) {
        int v;
        do {
            asm volatile("ld.acquire.gpu.global.b32 %0, [%1];"
                         : "=r"(v) : "l"(&g_done[b]) : "memory");
            if (v < 512) __nanosleep(64);
        } while (v < 512);
    }
    __syncthreads();

#pragma unroll
    for (int k = 0; k < 9; k++) {        // base-tap P rows (coalesced)
        const int row = h + k / 3 - 2;
        sP[k * 256 + t] = (row >= 0) ? g_P[k * PIX + b * (Hc * Wc) + row * Wc + t]
                                     : 0.0f;
    }
    __syncthreads();

    // ---- single wave: 9 offset-path P gathers + 9 offset-mask gathers ----
    float Vo[9], pmoff[9];
#pragma unroll
    for (int k = 0; k < 9; k++) {
        const int ky = k / 3;
        const int kx = k - ky * 3;
        const int yb = h + ky - 1;
        const int xb = w + kx - 1;
        const bool inb = (yb >= 0) & (yb < Hc) & (xb >= 0) & (xb < Wc);
        const int yi = inb ? yb : 0;
        const int xi = inb ? xb : 0;

        const float2 off2 = *reinterpret_cast<const float2*>(&soff[t * 18 + 2 * k]);

        // offset-path final coords (diff==1 case): clip(yi+off, 0, 255), floor
        const float yf = fminf(fmaxf((float)yi + off2.x, 0.0f), 255.0f);
        const float xf = fminf(fmaxf((float)xi + off2.y, 0.0f), 255.0f);
        const int y0 = (int)floorf(yf);
        const int x0 = (int)floorf(xf);
        Vo[k] = ((y0 >= 1) & (x0 >= 1))
                    ? Pb[k * PIX + (y0 - 1) * Wc + (x0 - 1)] : 0.0f;

        // mask at offset point (padded coords, floor + clip to [0,257])
        int yo = (int)floorf((float)yi + off2.x);
        int xo = (int)floorf((float)xi + off2.y);
        yo = min(max(yo, 0), Hc + 1);
        xo = min(max(xo, 0), Wc + 1);
        pmoff[k] = ((yo >= 1) & (yo <= Hc) & (xo >= 1) & (xo <= Wc))
                       ? mask[(yo - 1) * Wc + (xo - 1)] : 0.0f;
    }

    // ---- select + sum (smem-only consumers) ----
    float acc = __ldg(bias);
#pragma unroll
    for (int k = 0; k < 9; k++) {
        const int ky = k / 3;
        const int kx = k - ky * 3;
        const int yb = h + ky - 1;
        const int xb = w + kx - 1;
        const bool base_ok = (yb >= 1) & (yb < Hc) & (xb >= 1) & (xb < Wc);
        const float pmask = base_ok ? smask[ky * 256 + (w + kx - 2)] : 0.0f;
        const float Vb    = base_ok ? sP[k * 256 + (w + kx - 2)] : 0.0f;
        acc += (pmask != pmoff[k]) ? Vo[k] : Vb;
    }

    out[pixbase + t] = acc;

    // ---- self-cleaning counters (graph-replay deterministic) ----
    __syncthreads();
    if (t == 0) {
        const int old = atomicAdd(&g_p2done[b], 1);
        if (old == 255) {                 // 256 P2 blocks per batch
            atomicExch(&g_done[b], 0);
            atomicExch(&g_p2done[b], 0);
        }
    }
}

} // namespace

extern "C" void kernel_launch(void* const* d_in, const int* in_sizes, int n_in,
                              void* d_out, int out_size)
{
    const float* input  = (const float*)d_in[0];   // [4,256,256,64]
    const float* mask   = (const float*)d_in[1];   // [1,256,256,1]
    const float* offset = (const float*)d_in[2];   // [4,256,256,18]
    const float* kern   = (const float*)d_in[3];   // [3,3,64,1]
    const float* bias   = (const float*)d_in[4];   // [1]
    float* out = (float*)d_out;

    dcn_phase1<<<PIX / P1_T, P1_T>>>(input, kern);

    cudaLaunchConfig_t cfg = {};
    cfg.gridDim  = dim3(PIX / P2_T);
    cfg.blockDim = dim3(P2_T);
    cfg.dynamicSmemBytes = 0;
    cfg.stream = 0;
    cudaLaunchAttribute attrs[1];
    attrs[0].id = cudaLaunchAttributeProgrammaticStreamSerialization;
    attrs[0].val.programmaticStreamSerializationAllowed = 1;
    cfg.attrs = attrs;
    cfg.numAttrs = 1;
    cudaLaunchKernelEx(&cfg, dcn_phase2, mask, offset, bias, (float*)out);
}